// round 5
// baseline (speedup 1.0000x reference)
#include <cuda_runtime.h>

#define TPB   256
#define ROWS  64            // rows per block
#define HID   64
#define G3    192

// ---- shared memory layout (float offsets) ----
#define OFF_WHH  0              // 64*192 w_hh transposed [k][j]
#define OFF_WIH0 12288          // 192
#define OFF_WIH1 12480
#define OFF_BIH  12672
#define OFF_BHH  12864
#define OFF_WO0  13056          // 64
#define OFF_WO1  13120
#define OFF_HDB  13184
#define OFF_OUTB 13248          // 2
#define OFF_DYN  13252          // 16B aligned
#define OFF_HB0  OFF_DYN                 // 64*65 = 4160
#define OFF_HB1  (OFF_DYN + 4160)        // 4160
#define OFF_TOK  OFF_DYN                 // 64*68 = 4352 (aliases HB, phase-1 only)
#define OFF_W1   (OFF_DYN + 4352)        // 64*64 = 4096 (swizzled)
#define SMEM_FLOATS (OFF_DYN + 8448)     // 21700
#define SMEM_BYTES  (SMEM_FLOATS * 4)    // 86800

typedef unsigned long long ull;

__device__ __forceinline__ void fma2(ull& d, ull a, ull b) {
    asm("fma.rn.f32x2 %0, %1, %2, %0;" : "+l"(d) : "l"(a), "l"(b));
}
__device__ __forceinline__ ull pack2(float v) {
    ull r; asm("mov.b64 %0, {%1, %1};" : "=l"(r) : "f"(v)); return r;
}
__device__ __forceinline__ float2 unpack2(ull v) {
    float2 f; asm("mov.b64 {%0, %1}, %2;" : "=f"(f.x), "=f"(f.y) : "l"(v)); return f;
}
__device__ __forceinline__ float sigf(float v)  { return 1.0f / (1.0f + __expf(-v)); }
__device__ __forceinline__ float tanhfast(float v) {
    return 1.0f - 2.0f / (__expf(2.0f * v) + 1.0f);
}

__global__ void __launch_bounds__(TPB, 2)
gru_fused(const float* __restrict__ token,
          const float* __restrict__ whw,   // [64, NE]
          const float* __restrict__ whb,   // [64]
          const float* __restrict__ wih,   // [192, 2]
          const float* __restrict__ whhg,  // [192, 64]
          const float* __restrict__ bihg,  // [192]
          const float* __restrict__ bhhg,  // [192]
          const float* __restrict__ wow,   // [2, 64]
          const float* __restrict__ wob,   // [2]
          float* __restrict__ out,         // [B, T, 2]
          int B, int NE, int T)
{
    extern __shared__ float sm[];
    const int tid  = threadIdx.x;
    const int row0 = blockIdx.x * ROWS;
    const int p    = tid >> 3;            // row-pair 0..31
    const int q    = tid & 7;             // j-slice 0..7
    const int r0l  = 2 * p;
    const int r1l  = 2 * p + 1;

    // ---- stage GRU weights: transpose w_hh into [k][j] ----
    for (int idx = tid; idx < G3 * (HID / 4); idx += TPB) {
        int j  = idx >> 4;
        int k4 = idx & 15;
        float4 v = reinterpret_cast<const float4*>(whhg)[j * (HID / 4) + k4];
        sm[OFF_WHH + (k4 * 4 + 0) * G3 + j] = v.x;
        sm[OFF_WHH + (k4 * 4 + 1) * G3 + j] = v.y;
        sm[OFF_WHH + (k4 * 4 + 2) * G3 + j] = v.z;
        sm[OFF_WHH + (k4 * 4 + 3) * G3 + j] = v.w;
    }
    for (int j = tid; j < G3; j += TPB) {
        sm[OFF_WIH0 + j] = wih[j * 2 + 0];
        sm[OFF_WIH1 + j] = wih[j * 2 + 1];
        sm[OFF_BIH + j]  = bihg[j];
        sm[OFF_BHH + j]  = bhhg[j];
    }
    if (tid < HID) {
        sm[OFF_WO0 + tid] = wow[tid];
        sm[OFF_WO1 + tid] = wow[HID + tid];
        sm[OFF_HDB + tid] = whb[tid];
    }
    if (tid < 2) sm[OFF_OUTB + tid] = wob[tid];

    // ---------- phase 1: h0 = token @ whw^T + b ----------
    // thread: rows {2p, 2p+1}, j-set {q + 8*jj}; f32x2 accumulates (even k, odd k)
    ull acc1[2][8];
#pragma unroll
    for (int rr = 0; rr < 2; rr++)
#pragma unroll
        for (int jj = 0; jj < 8; jj++) acc1[rr][jj] = 0ull;

    const int nchunk = NE >> 6;
#pragma unroll 1
    for (int kc = 0; kc < nchunk; kc++) {
        __syncthreads();
        // token tile: 64 rows x 64 k (stride 68, float4-aligned)
        for (int i = tid; i < ROWS * 16; i += TPB) {
            int r  = i >> 4;
            int c4 = i & 15;
            int gr = row0 + r;
            float4 v = make_float4(0.f, 0.f, 0.f, 0.f);
            if (gr < B)
                v = reinterpret_cast<const float4*>(token)[(size_t)gr * (NE >> 2) + kc * 16 + c4];
            *reinterpret_cast<float4*>(&sm[OFF_TOK + r * 68 + c4 * 4]) = v;
        }
        // weight tile: 64 j x 64 k, XOR-swizzled (pk4 = k4 ^ (j&15)) for conflict-free reads
        for (int i = tid; i < HID * 16; i += TPB) {
            int j  = i >> 4;
            int k4 = i & 15;
            float4 v = reinterpret_cast<const float4*>(whw)[(size_t)j * (NE >> 2) + kc * 16 + k4];
            int pk4 = k4 ^ (j & 15);
            *reinterpret_cast<float4*>(&sm[OFF_W1 + j * 64 + pk4 * 4]) = v;
        }
        __syncthreads();
#pragma unroll
        for (int k4 = 0; k4 < 16; k4++) {
            ulonglong2 t0 = *reinterpret_cast<const ulonglong2*>(&sm[OFF_TOK + r0l * 68 + k4 * 4]);
            ulonglong2 t1 = *reinterpret_cast<const ulonglong2*>(&sm[OFF_TOK + r1l * 68 + k4 * 4]);
#pragma unroll
            for (int jj = 0; jj < 8; jj++) {
                int j  = q + 8 * jj;
                int pk = k4 ^ (q + ((jj & 1) << 3));
                ulonglong2 w = *reinterpret_cast<const ulonglong2*>(&sm[OFF_W1 + j * 64 + pk * 4]);
                fma2(acc1[0][jj], t0.x, w.x);
                fma2(acc1[0][jj], t0.y, w.y);
                fma2(acc1[1][jj], t1.x, w.x);
                fma2(acc1[1][jj], t1.y, w.y);
            }
        }
    }
    __syncthreads();   // all tile reads done before HB0 (aliased) is written

#pragma unroll
    for (int rr = 0; rr < 2; rr++)
#pragma unroll
        for (int jj = 0; jj < 8; jj++) {
            int j = q + 8 * jj;
            float2 v = unpack2(acc1[rr][jj]);
            sm[OFF_HB0 + (2 * p + rr) * 65 + j] = v.x + v.y + sm[OFF_HDB + j];
        }
    __syncwarp();

    // ---------- phase 2: GRU recurrence (rows private to warp, no block barriers) ----------
    float x0[2] = {0.f, 0.f}, x1[2] = {0.f, 0.f};
    const float outb0 = sm[OFF_OUTB + 0];
    const float outb1 = sm[OFF_OUTB + 1];
    int cur = 0;

#pragma unroll 1
    for (int step = 0; step < T; step++) {
        const float* hbc = sm + (cur ? OFF_HB1 : OFF_HB0);
        float*       hbn = sm + (cur ? OFF_HB0 : OFF_HB1);

        // acc[row][gate][s]; s covers j = (s>>1)*32 + q*4 + (s&1)*2 + {0,1}
        ull A[2][3][4];
#pragma unroll
        for (int rr = 0; rr < 2; rr++)
#pragma unroll
            for (int g = 0; g < 3; g++)
#pragma unroll
                for (int s = 0; s < 4; s++) A[rr][g][s] = 0ull;

#pragma unroll 8
        for (int k = 0; k < HID; k++) {
            ull h0p = pack2(hbc[r0l * 65 + k]);
            ull h1p = pack2(hbc[r1l * 65 + k]);
            const float* wk = &sm[OFF_WHH + k * G3 + q * 4];
#pragma unroll
            for (int g = 0; g < 3; g++) {
                ulonglong2 wa = *reinterpret_cast<const ulonglong2*>(wk + g * 64);
                ulonglong2 wb = *reinterpret_cast<const ulonglong2*>(wk + g * 64 + 32);
                fma2(A[0][g][0], h0p, wa.x);
                fma2(A[0][g][1], h0p, wa.y);
                fma2(A[0][g][2], h0p, wb.x);
                fma2(A[0][g][3], h0p, wb.y);
                fma2(A[1][g][0], h1p, wa.x);
                fma2(A[1][g][1], h1p, wa.y);
                fma2(A[1][g][2], h1p, wb.x);
                fma2(A[1][g][3], h1p, wb.y);
            }
        }

        float y0r[2] = {0.f, 0.f}, y1r[2] = {0.f, 0.f};
#pragma unroll
        for (int rr = 0; rr < 2; rr++) {
            const int toff = (2 * p + rr) * 65;
#pragma unroll
            for (int s = 0; s < 4; s++) {
                int jb = ((s >> 1) << 5) + (q << 2) + ((s & 1) << 1);
                float2 ar = unpack2(A[rr][0][s]);
                float2 az = unpack2(A[rr][1][s]);
                float2 an = unpack2(A[rr][2][s]);
#pragma unroll
                for (int c = 0; c < 2; c++) {
                    int j = jb + c;
                    float arv = c ? ar.y : ar.x;
                    float azv = c ? az.y : az.x;
                    float anv = c ? an.y : an.x;
                    float gir = fmaf(x1[rr], sm[OFF_WIH1 + j],
                               fmaf(x0[rr], sm[OFF_WIH0 + j],       sm[OFF_BIH + j]));
                    float giz = fmaf(x1[rr], sm[OFF_WIH1 + j + 64],
                               fmaf(x0[rr], sm[OFF_WIH0 + j + 64],  sm[OFF_BIH + j + 64]));
                    float gin = fmaf(x1[rr], sm[OFF_WIH1 + j + 128],
                               fmaf(x0[rr], sm[OFF_WIH0 + j + 128], sm[OFF_BIH + j + 128]));
                    float rg = sigf(gir + arv + sm[OFF_BHH + j]);
                    float ug = sigf(giz + azv + sm[OFF_BHH + j + 64]);
                    float ng = tanhfast(fmaf(rg, anv + sm[OFF_BHH + j + 128], gin));
                    float ho = hbc[toff + j];
                    float hn = fmaf(ug, ho - ng, ng);
                    hbn[toff + j] = hn;
                    y0r[rr] = fmaf(hn, sm[OFF_WO0 + j], y0r[rr]);
                    y1r[rr] = fmaf(hn, sm[OFF_WO1 + j], y1r[rr]);
                }
            }
        }
        // reduce y over the 8 q-lanes (butterfly keeps result in all lanes)
#pragma unroll
        for (int d = 1; d < 8; d <<= 1) {
            y0r[0] += __shfl_xor_sync(0xffffffffu, y0r[0], d);
            y1r[0] += __shfl_xor_sync(0xffffffffu, y1r[0], d);
            y0r[1] += __shfl_xor_sync(0xffffffffu, y0r[1], d);
            y1r[1] += __shfl_xor_sync(0xffffffffu, y1r[1], d);
        }
#pragma unroll
        for (int rr = 0; rr < 2; rr++) {
            x0[rr] += y0r[rr] + outb0;
            x1[rr] += y1r[rr] + outb1;
        }
        if (q == 0) {
#pragma unroll
            for (int rr = 0; rr < 2; rr++) {
                int grow = row0 + 2 * p + rr;
                if (grow < B)
                    *reinterpret_cast<float2*>(out + ((size_t)grow * T + step) * 2)
                        = make_float2(x0[rr], x1[rr]);
            }
        }
        __syncwarp();
        cur ^= 1;
    }
}

extern "C" void kernel_launch(void* const* d_in, const int* in_sizes, int n_in,
                              void* d_out, int out_size) {
    (void)n_in;
    const float* token = (const float*)d_in[0];
    const float* whw   = (const float*)d_in[1];
    const float* whb   = (const float*)d_in[2];
    const float* wih   = (const float*)d_in[3];
    const float* whh   = (const float*)d_in[4];
    const float* bih   = (const float*)d_in[5];
    const float* bhh   = (const float*)d_in[6];
    const float* wow   = (const float*)d_in[7];
    const float* wob   = (const float*)d_in[8];

    int NE = in_sizes[1] / HID;          // 1024
    int B  = in_sizes[0] / NE;           // 131072
    int T  = out_size / (B * 2);         // 10

    cudaFuncSetAttribute((const void*)gru_fused,
                         cudaFuncAttributeMaxDynamicSharedMemorySize, SMEM_BYTES);
    int grid = (B + ROWS - 1) / ROWS;
    gru_fused<<<grid, TPB, SMEM_BYTES>>>(token, whw, whb, wih, whh, bih, bhh,
                                         wow, wob, (float*)d_out, B, NE, T);
}

// round 6
// speedup vs baseline: 1.0010x; 1.0010x over previous
#include <cuda_runtime.h>

#define TPB   256
#define ROWS  64            // rows per block
#define HID   64
#define G3    192

// ---- shared memory layout (float offsets) ----
#define OFF_WHH  0              // 64*192 w_hh transposed [k][j]
#define OFF_WIH0 12288          // 192
#define OFF_WIH1 12480
#define OFF_BIH  12672
#define OFF_BHH  12864
#define OFF_WO0  13056          // 64
#define OFF_WO1  13120
#define OFF_HDB  13184
#define OFF_OUTB 13248          // 2
#define OFF_DYN  13252          // 16B aligned
#define OFF_HB0  OFF_DYN                 // 64*65 = 4160
#define OFF_HB1  (OFF_DYN + 4160)        // 4160
#define OFF_TOK  OFF_DYN                 // 64*68 = 4352 (aliases HB, phase-1 only)
#define OFF_W1   (OFF_DYN + 4352)        // 64*64 = 4096 (swizzled)
#define SMEM_FLOATS (OFF_DYN + 8448)     // 21700
#define SMEM_BYTES  (SMEM_FLOATS * 4)    // 86800

typedef unsigned long long ull;

__device__ __forceinline__ void fma2(ull& d, ull a, ull b) {
    asm("fma.rn.f32x2 %0, %1, %2, %0;" : "+l"(d) : "l"(a), "l"(b));
}
__device__ __forceinline__ ull pack2(float v) {
    ull r; asm("mov.b64 %0, {%1, %1};" : "=l"(r) : "f"(v)); return r;
}
__device__ __forceinline__ float2 unpack2(ull v) {
    float2 f; asm("mov.b64 {%0, %1}, %2;" : "=f"(f.x), "=f"(f.y) : "l"(v)); return f;
}
__device__ __forceinline__ float sigf(float v)  { return 1.0f / (1.0f + __expf(-v)); }
__device__ __forceinline__ float tanhfast(float v) {
    return 1.0f - 2.0f / (__expf(2.0f * v) + 1.0f);
}

__global__ void __launch_bounds__(TPB, 2)
gru_fused(const float* __restrict__ token,
          const float* __restrict__ whw,   // [64, NE]
          const float* __restrict__ whb,   // [64]
          const float* __restrict__ wih,   // [192, 2]
          const float* __restrict__ whhg,  // [192, 64]
          const float* __restrict__ bihg,  // [192]
          const float* __restrict__ bhhg,  // [192]
          const float* __restrict__ wow,   // [2, 64]
          const float* __restrict__ wob,   // [2]
          float* __restrict__ out,         // [B, T, 2]
          int B, int NE, int T)
{
    extern __shared__ float sm[];
    const int tid  = threadIdx.x;
    const int row0 = blockIdx.x * ROWS;
    const int p    = tid >> 3;            // row-pair 0..31
    const int q    = tid & 7;             // j-slice 0..7
    const int r0l  = 2 * p;
    const int r1l  = 2 * p + 1;

    // ---- stage GRU weights: transpose w_hh into [k][j] ----
    for (int idx = tid; idx < G3 * (HID / 4); idx += TPB) {
        int j  = idx >> 4;
        int k4 = idx & 15;
        float4 v = reinterpret_cast<const float4*>(whhg)[j * (HID / 4) + k4];
        sm[OFF_WHH + (k4 * 4 + 0) * G3 + j] = v.x;
        sm[OFF_WHH + (k4 * 4 + 1) * G3 + j] = v.y;
        sm[OFF_WHH + (k4 * 4 + 2) * G3 + j] = v.z;
        sm[OFF_WHH + (k4 * 4 + 3) * G3 + j] = v.w;
    }
    for (int j = tid; j < G3; j += TPB) {
        sm[OFF_WIH0 + j] = wih[j * 2 + 0];
        sm[OFF_WIH1 + j] = wih[j * 2 + 1];
        sm[OFF_BIH + j]  = bihg[j];
        sm[OFF_BHH + j]  = bhhg[j];
    }
    if (tid < HID) {
        sm[OFF_WO0 + tid] = wow[tid];
        sm[OFF_WO1 + tid] = wow[HID + tid];
        sm[OFF_HDB + tid] = whb[tid];
    }
    if (tid < 2) sm[OFF_OUTB + tid] = wob[tid];

    // ---------- phase 1: h0 = token @ whw^T + b ----------
    // thread: rows {2p, 2p+1}, j-set {q + 8*jj}; f32x2 accumulates (even k, odd k)
    ull acc1[2][8];
#pragma unroll
    for (int rr = 0; rr < 2; rr++)
#pragma unroll
        for (int jj = 0; jj < 8; jj++) acc1[rr][jj] = 0ull;

    const int nchunk = NE >> 6;
#pragma unroll 1
    for (int kc = 0; kc < nchunk; kc++) {
        __syncthreads();
        // token tile: 64 rows x 64 k (stride 68, float4-aligned)
        for (int i = tid; i < ROWS * 16; i += TPB) {
            int r  = i >> 4;
            int c4 = i & 15;
            int gr = row0 + r;
            float4 v = make_float4(0.f, 0.f, 0.f, 0.f);
            if (gr < B)
                v = reinterpret_cast<const float4*>(token)[(size_t)gr * (NE >> 2) + kc * 16 + c4];
            *reinterpret_cast<float4*>(&sm[OFF_TOK + r * 68 + c4 * 4]) = v;
        }
        // weight tile: 64 j x 64 k, XOR-swizzled (pk4 = k4 ^ (j&15)) for conflict-free reads
        for (int i = tid; i < HID * 16; i += TPB) {
            int j  = i >> 4;
            int k4 = i & 15;
            float4 v = reinterpret_cast<const float4*>(whw)[(size_t)j * (NE >> 2) + kc * 16 + k4];
            int pk4 = k4 ^ (j & 15);
            *reinterpret_cast<float4*>(&sm[OFF_W1 + j * 64 + pk4 * 4]) = v;
        }
        __syncthreads();
#pragma unroll
        for (int k4 = 0; k4 < 16; k4++) {
            ulonglong2 t0 = *reinterpret_cast<const ulonglong2*>(&sm[OFF_TOK + r0l * 68 + k4 * 4]);
            ulonglong2 t1 = *reinterpret_cast<const ulonglong2*>(&sm[OFF_TOK + r1l * 68 + k4 * 4]);
#pragma unroll
            for (int jj = 0; jj < 8; jj++) {
                int j  = q + 8 * jj;
                int pk = k4 ^ (q + ((jj & 1) << 3));
                ulonglong2 w = *reinterpret_cast<const ulonglong2*>(&sm[OFF_W1 + j * 64 + pk * 4]);
                fma2(acc1[0][jj], t0.x, w.x);
                fma2(acc1[0][jj], t0.y, w.y);
                fma2(acc1[1][jj], t1.x, w.x);
                fma2(acc1[1][jj], t1.y, w.y);
            }
        }
    }
    __syncthreads();   // all tile reads done before HB0 (aliased) is written

#pragma unroll
    for (int rr = 0; rr < 2; rr++)
#pragma unroll
        for (int jj = 0; jj < 8; jj++) {
            int j = q + 8 * jj;
            float2 v = unpack2(acc1[rr][jj]);
            sm[OFF_HB0 + (2 * p + rr) * 65 + j] = v.x + v.y + sm[OFF_HDB + j];
        }
    __syncwarp();

    // ---------- phase 2: GRU recurrence (rows private to warp, no block barriers) ----------
    float x0[2] = {0.f, 0.f}, x1[2] = {0.f, 0.f};
    const float outb0 = sm[OFF_OUTB + 0];
    const float outb1 = sm[OFF_OUTB + 1];
    int cur = 0;

#pragma unroll 1
    for (int step = 0; step < T; step++) {
        const float* hbc = sm + (cur ? OFF_HB1 : OFF_HB0);
        float*       hbn = sm + (cur ? OFF_HB0 : OFF_HB1);

        // acc[row][gate][s]; s covers j = (s>>1)*32 + q*4 + (s&1)*2 + {0,1}
        ull A[2][3][4];
#pragma unroll
        for (int rr = 0; rr < 2; rr++)
#pragma unroll
            for (int g = 0; g < 3; g++)
#pragma unroll
                for (int s = 0; s < 4; s++) A[rr][g][s] = 0ull;

#pragma unroll 8
        for (int k = 0; k < HID; k++) {
            ull h0p = pack2(hbc[r0l * 65 + k]);
            ull h1p = pack2(hbc[r1l * 65 + k]);
            const float* wk = &sm[OFF_WHH + k * G3 + q * 4];
#pragma unroll
            for (int g = 0; g < 3; g++) {
                ulonglong2 wa = *reinterpret_cast<const ulonglong2*>(wk + g * 64);
                ulonglong2 wb = *reinterpret_cast<const ulonglong2*>(wk + g * 64 + 32);
                fma2(A[0][g][0], h0p, wa.x);
                fma2(A[0][g][1], h0p, wa.y);
                fma2(A[0][g][2], h0p, wb.x);
                fma2(A[0][g][3], h0p, wb.y);
                fma2(A[1][g][0], h1p, wa.x);
                fma2(A[1][g][1], h1p, wa.y);
                fma2(A[1][g][2], h1p, wb.x);
                fma2(A[1][g][3], h1p, wb.y);
            }
        }

        float y0r[2] = {0.f, 0.f}, y1r[2] = {0.f, 0.f};
#pragma unroll
        for (int rr = 0; rr < 2; rr++) {
            const int toff = (2 * p + rr) * 65;
#pragma unroll
            for (int s = 0; s < 4; s++) {
                int jb = ((s >> 1) << 5) + (q << 2) + ((s & 1) << 1);
                float2 ar = unpack2(A[rr][0][s]);
                float2 az = unpack2(A[rr][1][s]);
                float2 an = unpack2(A[rr][2][s]);
#pragma unroll
                for (int c = 0; c < 2; c++) {
                    int j = jb + c;
                    float arv = c ? ar.y : ar.x;
                    float azv = c ? az.y : az.x;
                    float anv = c ? an.y : an.x;
                    float gir = fmaf(x1[rr], sm[OFF_WIH1 + j],
                               fmaf(x0[rr], sm[OFF_WIH0 + j],       sm[OFF_BIH + j]));
                    float giz = fmaf(x1[rr], sm[OFF_WIH1 + j + 64],
                               fmaf(x0[rr], sm[OFF_WIH0 + j + 64],  sm[OFF_BIH + j + 64]));
                    float gin = fmaf(x1[rr], sm[OFF_WIH1 + j + 128],
                               fmaf(x0[rr], sm[OFF_WIH0 + j + 128], sm[OFF_BIH + j + 128]));
                    float rg = sigf(gir + arv + sm[OFF_BHH + j]);
                    float ug = sigf(giz + azv + sm[OFF_BHH + j + 64]);
                    float ng = tanhfast(fmaf(rg, anv + sm[OFF_BHH + j + 128], gin));
                    float ho = hbc[toff + j];
                    float hn = fmaf(ug, ho - ng, ng);
                    hbn[toff + j] = hn;
                    y0r[rr] = fmaf(hn, sm[OFF_WO0 + j], y0r[rr]);
                    y1r[rr] = fmaf(hn, sm[OFF_WO1 + j], y1r[rr]);
                }
            }
        }
        // reduce y over the 8 q-lanes (butterfly keeps result in all lanes)
#pragma unroll
        for (int d = 1; d < 8; d <<= 1) {
            y0r[0] += __shfl_xor_sync(0xffffffffu, y0r[0], d);
            y1r[0] += __shfl_xor_sync(0xffffffffu, y1r[0], d);
            y0r[1] += __shfl_xor_sync(0xffffffffu, y0r[1], d);
            y1r[1] += __shfl_xor_sync(0xffffffffu, y1r[1], d);
        }
#pragma unroll
        for (int rr = 0; rr < 2; rr++) {
            x0[rr] += y0r[rr] + outb0;
            x1[rr] += y1r[rr] + outb1;
        }
        if (q == 0) {
#pragma unroll
            for (int rr = 0; rr < 2; rr++) {
                int grow = row0 + 2 * p + rr;
                if (grow < B)
                    *reinterpret_cast<float2*>(out + ((size_t)grow * T + step) * 2)
                        = make_float2(x0[rr], x1[rr]);
            }
        }
        __syncwarp();
        cur ^= 1;
    }
}

extern "C" void kernel_launch(void* const* d_in, const int* in_sizes, int n_in,
                              void* d_out, int out_size) {
    (void)n_in;
    const float* token = (const float*)d_in[0];
    const float* whw   = (const float*)d_in[1];
    const float* whb   = (const float*)d_in[2];
    const float* wih   = (const float*)d_in[3];
    const float* whh   = (const float*)d_in[4];
    const float* bih   = (const float*)d_in[5];
    const float* bhh   = (const float*)d_in[6];
    const float* wow   = (const float*)d_in[7];
    const float* wob   = (const float*)d_in[8];

    int NE = in_sizes[1] / HID;          // 1024
    int B  = in_sizes[0] / NE;           // 131072
    int T  = out_size / (B * 2);         // 10

    cudaFuncSetAttribute((const void*)gru_fused,
                         cudaFuncAttributeMaxDynamicSharedMemorySize, SMEM_BYTES);
    int grid = (B + ROWS - 1) / ROWS;
    gru_fused<<<grid, TPB, SMEM_BYTES>>>(token, whw, whb, wih, whh, bih, bhh,
                                         wow, wob, (float*)d_out, B, NE, T);
}

// round 8
// speedup vs baseline: 1.3551x; 1.3537x over previous
#include <cuda_runtime.h>

#define TPB   256
#define RPW   8              // rows per warp
#define ROWS  64             // rows per block (8 warps)
#define HID   64
#define G3    192

// ---- shared memory layout (float offsets) ----
#define OFF_WHH  0                   // [k][192]  64*192 = 12288
#define OFF_WIH0 12288               // 192
#define OFF_WIH1 (12288+192)
#define OFF_BIH  (12288+384)
#define OFF_BHH  (12288+576)
#define OFF_WO0  (12288+768)         // 64
#define OFF_WO1  (12288+832)
#define OFF_HDB  (12288+896)
#define OFF_OUTB (12288+960)         // 2  (ends at 13250)
#define OFF_TOK  13252               // 64*68 = 4352   (starts AFTER the constants!)
#define OFF_W1   (13252+4352)        // 17604: 32*132 = 4224  k-pair interleaved
#define OFF_HB   (17604+4224)        // 21828: 64*64 = 4096
#define SMEM_FLOATS (OFF_HB + 4096)  // 25924
#define SMEM_BYTES  (SMEM_FLOATS*4)  // 103696

typedef unsigned long long ull;

__device__ __forceinline__ void fma2(ull& d, ull a, ull b) {
    asm("fma.rn.f32x2 %0, %1, %2, %0;" : "+l"(d) : "l"(a), "l"(b));
}
__device__ __forceinline__ ull pack2(float v) {
    ull r; asm("mov.b64 %0, {%1, %1};" : "=l"(r) : "f"(v)); return r;
}
__device__ __forceinline__ float2 unpack2(ull v) {
    float2 f; asm("mov.b64 {%0, %1}, %2;" : "=f"(f.x), "=f"(f.y) : "l"(v)); return f;
}
__device__ __forceinline__ float sigf(float v)  { return 1.0f / (1.0f + __expf(-v)); }
__device__ __forceinline__ float tanhfast(float v) {
    return 1.0f - 2.0f / (__expf(2.0f * v) + 1.0f);
}

__global__ void __launch_bounds__(TPB, 2)
gru_fused(const float* __restrict__ token,
          const float* __restrict__ whw,   // [64, NE]
          const float* __restrict__ whb,   // [64]
          const float* __restrict__ wih,   // [192, 2]
          const float* __restrict__ whhg,  // [192, 64]
          const float* __restrict__ bihg,  // [192]
          const float* __restrict__ bhhg,  // [192]
          const float* __restrict__ wow,   // [2, 64]
          const float* __restrict__ wob,   // [2]
          float* __restrict__ out,         // [B, T, 2]
          int B, int NE, int T)
{
    extern __shared__ float sm[];
    const int tid  = threadIdx.x;
    const int wid  = tid >> 5;
    const int lan  = tid & 31;
    const int m0   = 2 * lan;          // this lane's hidden-unit pair
    const int row0 = blockIdx.x * ROWS;
    const int wrow = wid * RPW;        // warp's first local row

    // ---- stage GRU weights: transpose w_hh into [k][j] (stride 192) ----
    for (int idx = tid; idx < G3 * (HID / 4); idx += TPB) {
        int j  = idx >> 4;
        int k4 = idx & 15;
        float4 v = reinterpret_cast<const float4*>(whhg)[j * (HID / 4) + k4];
        sm[OFF_WHH + (k4 * 4 + 0) * G3 + j] = v.x;
        sm[OFF_WHH + (k4 * 4 + 1) * G3 + j] = v.y;
        sm[OFF_WHH + (k4 * 4 + 2) * G3 + j] = v.z;
        sm[OFF_WHH + (k4 * 4 + 3) * G3 + j] = v.w;
    }
    for (int j = tid; j < G3; j += TPB) {
        sm[OFF_WIH0 + j] = wih[j * 2 + 0];
        sm[OFF_WIH1 + j] = wih[j * 2 + 1];
        sm[OFF_BIH + j]  = bihg[j];
        sm[OFF_BHH + j]  = bhhg[j];
    }
    if (tid < HID) {
        sm[OFF_WO0 + tid] = wow[tid];
        sm[OFF_WO1 + tid] = wow[HID + tid];
        sm[OFF_HDB + tid] = whb[tid];
    }
    if (tid < 2) sm[OFF_OUTB + tid] = wob[tid];

    // ---------- phase 1: h0 = token @ whw^T + b ----------
    // lane owns outputs m0, m0+1 for its warp's 8 rows.
    // acc[r][mi] is f32x2 over k-parity (even-k sum, odd-k sum).
    ull acc[RPW][2];
#pragma unroll
    for (int r = 0; r < RPW; r++) { acc[r][0] = 0ull; acc[r][1] = 0ull; }

    const int nchunk = NE >> 6;
#pragma unroll 1
    for (int kc = 0; kc < nchunk; kc++) {
        __syncthreads();
        // token tile: 64 rows x 64 k, stride 68
        for (int i = tid; i < ROWS * 16; i += TPB) {
            int r  = i >> 4;
            int c4 = i & 15;
            int gr = row0 + r;
            float4 v = make_float4(0.f, 0.f, 0.f, 0.f);
            if (gr < B)
                v = reinterpret_cast<const float4*>(token)[(size_t)gr * (NE >> 2) + kc * 16 + c4];
            *reinterpret_cast<float4*>(&sm[OFF_TOK + r * 68 + c4 * 4]) = v;
        }
        // weight tile, k-pair interleaved: w1[k2*132 + 2*m + par] = whw[m][2*k2+par]
        for (int i = tid; i < HID * 16; i += TPB) {
            int m  = i >> 4;
            int k4 = i & 15;
            float4 v = reinterpret_cast<const float4*>(whw)[(size_t)m * (NE >> 2) + kc * 16 + k4];
            sm[OFF_W1 + (2 * k4 + 0) * 132 + 2 * m + 0] = v.x;
            sm[OFF_W1 + (2 * k4 + 0) * 132 + 2 * m + 1] = v.y;
            sm[OFF_W1 + (2 * k4 + 1) * 132 + 2 * m + 0] = v.z;
            sm[OFF_W1 + (2 * k4 + 1) * 132 + 2 * m + 1] = v.w;
        }
        __syncthreads();
#pragma unroll
        for (int k2e = 0; k2e < 32; k2e += 2) {
            // wv0: k-pair {2*k2e, 2*k2e+1}; wv1: next k-pair; .x for m0, .y for m0+1
            ulonglong2 wv0 = *reinterpret_cast<const ulonglong2*>(&sm[OFF_W1 + k2e * 132 + 4 * lan]);
            ulonglong2 wv1 = *reinterpret_cast<const ulonglong2*>(&sm[OFF_W1 + (k2e + 1) * 132 + 4 * lan]);
#pragma unroll
            for (int r = 0; r < RPW; r++) {
                ulonglong2 tp = *reinterpret_cast<const ulonglong2*>(
                    &sm[OFF_TOK + (wrow + r) * 68 + k2e * 2]);
                fma2(acc[r][0], tp.x, wv0.x);
                fma2(acc[r][1], tp.x, wv0.y);
                fma2(acc[r][0], tp.y, wv1.x);
                fma2(acc[r][1], tp.y, wv1.y);
            }
        }
    }
    __syncthreads();

    // finalize h0 into warp-private h buffer
    {
        float hd0 = sm[OFF_HDB + m0];
        float hd1 = sm[OFF_HDB + m0 + 1];
#pragma unroll
        for (int r = 0; r < RPW; r++) {
            float2 a0 = unpack2(acc[r][0]);
            float2 a1 = unpack2(acc[r][1]);
            *reinterpret_cast<float2*>(&sm[OFF_HB + (wrow + r) * 64 + m0])
                = make_float2(a0.x + a0.y + hd0, a1.x + a1.y + hd1);
        }
    }
    __syncwarp();

    // ---------- phase 2: GRU recurrence (warp-private rows, no block barriers) ----------
    float x0[RPW], x1[RPW];
#pragma unroll
    for (int r = 0; r < RPW; r++) { x0[r] = 0.f; x1[r] = 0.f; }

#pragma unroll 1
    for (int step = 0; step < T; step++) {
        // gate preactivation accumulators: A[row][gate] = f32x2 over {m0, m0+1}
        ull A[RPW][3];
#pragma unroll
        for (int r = 0; r < RPW; r++) { A[r][0] = 0ull; A[r][1] = 0ull; A[r][2] = 0ull; }

#pragma unroll
        for (int k4 = 0; k4 < 16; k4++) {
            float4 hv[RPW];
#pragma unroll
            for (int r = 0; r < RPW; r++)
                hv[r] = *reinterpret_cast<const float4*>(&sm[OFF_HB + (wrow + r) * 64 + k4 * 4]);
#pragma unroll
            for (int c = 0; c < 4; c++) {
                const float* wk = &sm[OFF_WHH + (k4 * 4 + c) * G3 + m0];
                ull wr = *reinterpret_cast<const ull*>(wk);
                ull wz = *reinterpret_cast<const ull*>(wk + 64);
                ull wn = *reinterpret_cast<const ull*>(wk + 128);
#pragma unroll
                for (int r = 0; r < RPW; r++) {
                    float hc = (c == 0) ? hv[r].x : (c == 1) ? hv[r].y : (c == 2) ? hv[r].z : hv[r].w;
                    ull hp = pack2(hc);
                    fma2(A[r][0], hp, wr);
                    fma2(A[r][1], hp, wz);
                    fma2(A[r][2], hp, wn);
                }
            }
        }

        // gate math: lane-local for m0, m0+1
        float2 wi0r = *reinterpret_cast<const float2*>(&sm[OFF_WIH0 + m0]);
        float2 wi0z = *reinterpret_cast<const float2*>(&sm[OFF_WIH0 + 64 + m0]);
        float2 wi0n = *reinterpret_cast<const float2*>(&sm[OFF_WIH0 + 128 + m0]);
        float2 wi1r = *reinterpret_cast<const float2*>(&sm[OFF_WIH1 + m0]);
        float2 wi1z = *reinterpret_cast<const float2*>(&sm[OFF_WIH1 + 64 + m0]);
        float2 wi1n = *reinterpret_cast<const float2*>(&sm[OFF_WIH1 + 128 + m0]);
        float2 bir  = *reinterpret_cast<const float2*>(&sm[OFF_BIH + m0]);
        float2 biz  = *reinterpret_cast<const float2*>(&sm[OFF_BIH + 64 + m0]);
        float2 bin  = *reinterpret_cast<const float2*>(&sm[OFF_BIH + 128 + m0]);
        float2 bhr  = *reinterpret_cast<const float2*>(&sm[OFF_BHH + m0]);
        float2 bhz  = *reinterpret_cast<const float2*>(&sm[OFF_BHH + 64 + m0]);
        float2 bhn  = *reinterpret_cast<const float2*>(&sm[OFF_BHH + 128 + m0]);
        float2 wo0p = *reinterpret_cast<const float2*>(&sm[OFF_WO0 + m0]);
        float2 wo1p = *reinterpret_cast<const float2*>(&sm[OFF_WO1 + m0]);
        float ob0 = sm[OFF_OUTB + 0];
        float ob1 = sm[OFF_OUTB + 1];

        float y0[RPW], y1[RPW];
#pragma unroll
        for (int r = 0; r < RPW; r++) {
            float2 ar = unpack2(A[r][0]);
            float2 az = unpack2(A[r][1]);
            float2 an = unpack2(A[r][2]);
            float2 ho = *reinterpret_cast<const float2*>(&sm[OFF_HB + (wrow + r) * 64 + m0]);

            float gir0 = fmaf(x1[r], wi1r.x, fmaf(x0[r], wi0r.x, bir.x));
            float giz0 = fmaf(x1[r], wi1z.x, fmaf(x0[r], wi0z.x, biz.x));
            float gin0 = fmaf(x1[r], wi1n.x, fmaf(x0[r], wi0n.x, bin.x));
            float rg0 = sigf(gir0 + ar.x + bhr.x);
            float ug0 = sigf(giz0 + az.x + bhz.x);
            float ng0 = tanhfast(fmaf(rg0, an.x + bhn.x, gin0));
            float hn0 = fmaf(ug0, ho.x - ng0, ng0);

            float gir1 = fmaf(x1[r], wi1r.y, fmaf(x0[r], wi0r.y, bir.y));
            float giz1 = fmaf(x1[r], wi1z.y, fmaf(x0[r], wi0z.y, biz.y));
            float gin1 = fmaf(x1[r], wi1n.y, fmaf(x0[r], wi0n.y, bin.y));
            float rg1 = sigf(gir1 + ar.y + bhr.y);
            float ug1 = sigf(giz1 + az.y + bhz.y);
            float ng1 = tanhfast(fmaf(rg1, an.y + bhn.y, gin1));
            float hn1 = fmaf(ug1, ho.y - ng1, ng1);

            *reinterpret_cast<float2*>(&sm[OFF_HB + (wrow + r) * 64 + m0])
                = make_float2(hn0, hn1);
            y0[r] = fmaf(hn1, wo0p.y, hn0 * wo0p.x);
            y1[r] = fmaf(hn1, wo1p.y, hn0 * wo1p.x);
        }

        // reduce y over 32 lanes (butterfly; every lane ends with full sums)
#pragma unroll
        for (int d = 1; d < 32; d <<= 1) {
#pragma unroll
            for (int r = 0; r < RPW; r++) {
                y0[r] += __shfl_xor_sync(0xffffffffu, y0[r], d);
                y1[r] += __shfl_xor_sync(0xffffffffu, y1[r], d);
            }
        }
#pragma unroll
        for (int r = 0; r < RPW; r++) {
            x0[r] += y0[r] + ob0;
            x1[r] += y1[r] + ob1;
        }

        // lanes 0..7 write their row's output (x replicated across lanes)
        if (lan < RPW) {
            float ox0 = x0[0], ox1 = x1[0];
#pragma unroll
            for (int r = 1; r < RPW; r++)
                if (lan == r) { ox0 = x0[r]; ox1 = x1[r]; }
            int grow = row0 + wrow + lan;
            if (grow < B)
                *reinterpret_cast<float2*>(out + ((size_t)grow * T + step) * 2)
                    = make_float2(ox0, ox1);
        }
        __syncwarp();
    }
}

extern "C" void kernel_launch(void* const* d_in, const int* in_sizes, int n_in,
                              void* d_out, int out_size) {
    (void)n_in;
    const float* token = (const float*)d_in[0];
    const float* whw   = (const float*)d_in[1];
    const float* whb   = (const float*)d_in[2];
    const float* wih   = (const float*)d_in[3];
    const float* whh   = (const float*)d_in[4];
    const float* bih   = (const float*)d_in[5];
    const float* bhh   = (const float*)d_in[6];
    const float* wow   = (const float*)d_in[7];
    const float* wob   = (const float*)d_in[8];

    int NE = in_sizes[1] / HID;          // 1024
    int B  = in_sizes[0] / NE;           // 131072
    int T  = out_size / (B * 2);         // 10

    cudaFuncSetAttribute((const void*)gru_fused,
                         cudaFuncAttributeMaxDynamicSharedMemorySize, SMEM_BYTES);
    int grid = (B + ROWS - 1) / ROWS;
    gru_fused<<<grid, TPB, SMEM_BYTES>>>(token, whw, whb, wih, whh, bih, bhh,
                                         wow, wob, (float*)d_out, B, NE, T);
}